// round 14
// baseline (speedup 1.0000x reference)
#include <cuda_runtime.h>
#include <cuda_bf16.h>
#include <cstdint>

// BilateralFilter (SqueezeSeg): out[b,z,a,k,c] = exp(-||x[b,z,a]-nbr_k||^2 / (2*theta_c^2))
// B=16, Z=64, A=512, K=14 (3x5 minus center), theta=[.015,.015,.01,.01]
// -> per (pixel,k) output float4 = (e1,e1,e2,e2), only 2 distinct exps.
//
// R14: two kernels.
//  1) pad_kernel: repack float3 input into float4 g_pad[16][66][516] with the
//     zero halo baked in (8.7 MB static __device__ scratch, ~15 MB traffic).
//  2) bilateral_kernel: NO smem, NO barriers, NO predication. Per output:
//     1 aligned LDG.128 center (near-broadcast) + 1 aligned LDG.128 neighbor
//     + 1 coalesced STG.128. Input L2-resident + L1-hot; warps independent.

#define BB 16
#define ZZ 64
#define AA 512
#define KK 14

#define PZ (ZZ + 2)           // 66 padded rows
#define PA (AA + 4)           // 516 padded cols
#define NPAD (BB * PZ * PA)   // 544,896 float4

#define TA 256                // pixels (a) per CTA
#define NT 896                // threads
#define PT 4                  // outputs per thread per z-row
#define ZC 4                  // z-rows per CTA

__device__ float4 g_pad[NPAD];   // 8.7 MB scratch

__global__ void pad_kernel(const float* __restrict__ x)
{
    const int idx = blockIdx.x * blockDim.x + threadIdx.x;
    if (idx >= NPAD) return;
    const int b  = idx / (PZ * PA);
    const int r  = idx - b * (PZ * PA);
    const int zp = r / PA;
    const int ap = r - zp * PA;
    const int z = zp - 1;
    const int a = ap - 2;
    float4 v = make_float4(0.f, 0.f, 0.f, 0.f);
    if (z >= 0 && z < ZZ && a >= 0 && a < AA) {
        const float* p = x + ((size_t)((b * ZZ + z) * AA + a)) * 3;
        v.x = p[0]; v.y = p[1]; v.z = p[2];
    }
    g_pad[idx] = v;
}

__global__ __launch_bounds__(NT, 2)
void bilateral_kernel(float4* __restrict__ out)
{
    const int tid = threadIdx.x;
    const int a0 = blockIdx.x * TA;
    const int z0 = blockIdx.y * ZC;
    const int b  = blockIdx.z;

    // ---- decode once: k, (i,j) invariant for this thread ----
    const int p0 = tid / KK;          // 0..63
    const int k  = tid - p0 * KK;     // 0..13
    const int kk = k + (k >= 7);      // skip center (flat 7)
    const int i  = kk / 5;            // 0..2
    const int j  = kk - i * 5;        // 0..4

    const float C1 = -1.0f / (2.0f * 0.015f * 0.015f);
    const float C2 = -1.0f / (2.0f * 0.01f  * 0.01f );

    const float4* __restrict__ xb = g_pad + (size_t)b * PZ * PA;
    float4* ob = out + ((size_t)((b * ZZ + z0) * AA + a0)) * KK + tid;

    #pragma unroll 1
    for (int z = z0; z < z0 + ZC; ++z) {
        // padded coords: pixel (z,a) -> xb[(z+1)*PA + a+2]
        const float4* rowC = xb + (size_t)(z + 1) * PA + 2 + a0 + p0;
        const float4* rowN = xb + (size_t)(z + i) * PA + j + a0 + p0;

        #pragma unroll
        for (int it = 0; it < PT; ++it) {
            const float4 c4 = rowC[it * 64];
            const float4 n4 = rowN[it * 64];
            const float dx = c4.x - n4.x;
            const float dy = c4.y - n4.y;
            const float dz = c4.z - n4.z;
            const float d2 = fmaf(dz, dz, fmaf(dy, dy, dx * dx));
            const float e1 = __expf(d2 * C1);
            const float e2 = __expf(d2 * C2);
            __stcs(&ob[it * NT], make_float4(e1, e1, e2, e2));
        }

        ob += (size_t)AA * KK;
    }
}

extern "C" void kernel_launch(void* const* d_in, const int* in_sizes, int n_in,
                              void* d_out, int out_size)
{
    (void)in_sizes; (void)n_in; (void)out_size;
    const float* x = (const float*)d_in[0];
    float4* out = (float4*)d_out;

    pad_kernel<<<(NPAD + 255) / 256, 256>>>(x);

    dim3 grid(AA / TA, ZZ / ZC, BB);   // 2 x 16 x 16 = 512 CTAs
    dim3 block(NT);                    // 896 threads
    bilateral_kernel<<<grid, block>>>(out);
}

// round 15
// speedup vs baseline: 1.0743x; 1.0743x over previous
#include <cuda_runtime.h>
#include <cuda_bf16.h>
#include <cstdint>

// BilateralFilter (SqueezeSeg): out[b,z,a,k,c] = exp(-||x[b,z,a]-nbr_k||^2 / (2*theta_c^2))
// B=16, Z=64, A=512, K=14 (3x5 minus center), theta=[.015,.015,.01,.01]
// -> per (pixel,k) output float4 = (e1,e1,e2,e2), only 2 distinct exps.
//
// R15: R6 base (AoS float4 tile, TA=256/896thr/occ2/ZC=8, 1 barrier/z-step,
// prefetch depth 2, __expf) with k-PAIRING: each thread owns k=2*k2,2*k2+1
// (7 threads/pixel). Per pair: ONE shared center LDS + 2 neighbor LDS +
// ONE 256-bit st.global.cs.v8.f32 (lane-consecutive 32B -> coalesced).
// MIO instructions per z-step: 8 vs R6's 12.

#define BB 16
#define ZZ 64
#define AA 512
#define KK 14

#define TA 256                // pixels (a) per CTA
#define NT 896                // threads (128 pixel-slots x 7 k-pairs)
#define HW (TA + 4)           // 260 halo width
#define ZC 8                  // z-rows per CTA

__global__ __launch_bounds__(NT, 2)
void bilateral_kernel(const float* __restrict__ x, float* __restrict__ out)
{
    __shared__ float4 tile[4][HW];   // circular rows, slot = z & 3

    const int tid = threadIdx.x;
    const int a0 = blockIdx.x * TA;
    const int z0 = blockIdx.y * ZC;
    const int b  = blockIdx.z;

    // ---- prologue: rows z0-1, z0, z0+1 into their slots ----
    for (int idx = tid; idx < 3 * HW; idx += NT) {
        const int r = idx / HW;
        const int c = idx - r * HW;
        const int gz = z0 + r - 1;
        const int ga = a0 + c - 2;
        float4 v = make_float4(0.f, 0.f, 0.f, 0.f);
        if (gz >= 0 && gz < ZZ && ga >= 0 && ga < AA) {
            const float* p = x + ((size_t)((b * ZZ + gz) * AA + ga)) * 3;
            v.x = p[0]; v.y = p[1]; v.z = p[2];
        }
        tile[gz & 3][c] = v;
    }

    // ---- decode once: pixel slot p0 and k-pair (2*k2, 2*k2+1) ----
    const int p0 = tid / 7;           // 0..127
    const int k2 = tid - p0 * 7;      // 0..6
    const int k0 = 2 * k2;            // even k
    const int k1 = k0 + 1;            // odd k
    const int kk0 = k0 + (k0 >= 7);   // flat 3x5 index, center (7) skipped
    const int kk1 = k1 + (k1 >= 7);
    const int i0 = kk0 / 5, j0 = kk0 - i0 * 5;
    const int i1 = kk1 / 5, j1 = kk1 - i1 * 5;

    const float C1 = -1.0f / (2.0f * 0.015f * 0.015f);
    const float C2 = -1.0f / (2.0f * 0.01f  * 0.01f );

    // float index: ((b*ZZ+z)*AA + a0 + p)*56 + k2*8 ; thread offset p0*56+k2*8
    float* ob = out + ((size_t)((b * ZZ + z0) * AA + a0)) * (KK * 4)
                    + p0 * 56 + k2 * 8;

    // ---- initial register prefetch of row z0+2 ----
    const int ga_pf = a0 + tid - 2;
    const bool lane_pf = (tid < HW) && (ga_pf >= 0) && (ga_pf < AA);
    float px = 0.f, py = 0.f, pz = 0.f;
    {
        const int gz = z0 + 2;
        if (lane_pf && gz < ZZ) {
            const float* p = x + ((size_t)((b * ZZ + gz) * AA + ga_pf)) * 3;
            px = p[0]; py = p[1]; pz = p[2];
        }
    }

    #pragma unroll 1
    for (int z = z0; z < z0 + ZC; ++z) {
        __syncthreads();   // orders prior STS before this step's reads,
                           // and prior reads of slot (z+2)&3 before this STS

        // ---- STS prefetched row z+2 (slot disjoint from compute slots) ----
        if (tid < HW && z + 2 <= z0 + ZC)
            tile[(z + 2) & 3][tid] = make_float4(px, py, pz, 0.f);

        // ---- issue LDG prefetch for row z+3 (consumed next step) ----
        px = 0.f; py = 0.f; pz = 0.f;
        {
            const int gz = z + 3;
            if (lane_pf && gz < ZZ && z + 3 <= z0 + ZC) {
                const float* p = x + ((size_t)((b * ZZ + gz) * AA + ga_pf)) * 3;
                px = p[0]; py = p[1]; pz = p[2];
            }
        }

        // ---- compute row z: 2 pixel-groups x k-pair ----
        const int sc  = z & 3;
        const int sn0 = (z - 1 + i0) & 3;
        const int sn1 = (z - 1 + i1) & 3;
        #pragma unroll
        for (int it = 0; it < 2; ++it) {
            const int p = p0 + it * 128;
            const float4 c4 = tile[sc][p + 2];         // shared by both k's
            const float4 na = tile[sn0][p + j0];
            const float4 nb = tile[sn1][p + j1];

            const float dxa = c4.x - na.x, dya = c4.y - na.y, dza = c4.z - na.z;
            const float d2a = fmaf(dza, dza, fmaf(dya, dya, dxa * dxa));
            const float dxb = c4.x - nb.x, dyb = c4.y - nb.y, dzb = c4.z - nb.z;
            const float d2b = fmaf(dzb, dzb, fmaf(dyb, dyb, dxb * dxb));

            const float e1a = __expf(d2a * C1);
            const float e2a = __expf(d2a * C2);
            const float e1b = __expf(d2b * C1);
            const float e2b = __expf(d2b * C2);

            asm volatile(
                "st.global.cs.v8.f32 [%0], {%1,%2,%3,%4,%5,%6,%7,%8};"
                :: "l"(ob + (size_t)it * 128 * 56),
                   "f"(e1a), "f"(e1a), "f"(e2a), "f"(e2a),
                   "f"(e1b), "f"(e1b), "f"(e2b), "f"(e2b)
                : "memory");
        }

        ob += (size_t)AA * KK * 4;
    }
}

extern "C" void kernel_launch(void* const* d_in, const int* in_sizes, int n_in,
                              void* d_out, int out_size)
{
    (void)in_sizes; (void)n_in; (void)out_size;
    const float* x = (const float*)d_in[0];
    float* out = (float*)d_out;

    dim3 grid(AA / TA, ZZ / ZC, BB);   // 2 x 8 x 16 = 256 CTAs
    dim3 block(NT);                    // 896 threads
    bilateral_kernel<<<grid, block>>>(x, out);
}